// round 8
// baseline (speedup 1.0000x reference)
#include <cuda_runtime.h>
#include <cuda_bf16.h>
#include <math.h>
#include <stdint.h>

#define NNODES 50000
#define NEDG   400000
#define ETOT   450000
#define WID    256
#define NG     256
#define NPAD   50048        // 391 * 128
#define MTILES 391
#define DCAP   256

// ---------------- scratch globals ----------------
__device__ float g_featA[(size_t)NNODES * WID];
__device__ float g_h[(size_t)NNODES * WID];
__device__ float g_als[NNODES * 4];
__device__ float g_ald[NNODES * 4];
__device__ float g_esc[(size_t)ETOT * 4];    // fallback only (deg > DCAP)
__device__ int   g_dst[ETOT];
__device__ int   g_srcE[ETOT];
__device__ int   g_scsr[ETOT];
__device__ int   g_deg[NNODES];
__device__ int   g_rowptr[NNODES + 1];
__device__ int   g_cursor[NNODES];
__device__ int   g_i64flag;
__device__ int   g_incl[NNODES];
__device__ int   g_bsum[64];
__device__ int   g_boff[64];
// bf16 split operands (zero-init covers M padding)
__device__ __align__(16) __nv_bfloat16 g_Ahi[(size_t)NPAD * WID];
__device__ __align__(16) __nv_bfloat16 g_Alo[(size_t)NPAD * WID];
__device__ __align__(16) __nv_bfloat16 g_Bhi[WID * WID];   // [N=256][K]
__device__ __align__(16) __nv_bfloat16 g_Blo[WID * WID];

// ---------------- helpers ----------------
__device__ __forceinline__ uint32_t smem_u32(const void* p) {
    uint32_t a;
    asm("{ .reg .u64 t; cvta.to.shared.u64 t, %1; cvt.u32.u64 %0, t; }" : "=r"(a) : "l"(p));
    return a;
}
__device__ __forceinline__ void cp16(uint32_t s, const void* g) {
    asm volatile("cp.async.cg.shared.global [%0], [%1], 16;" :: "r"(s), "l"(g));
}
#define CP_COMMIT()  asm volatile("cp.async.commit_group;" ::: "memory")
#define CP_WAIT(n)   asm volatile("cp.async.wait_group %0;" :: "n"(n) : "memory")

__device__ __forceinline__ void mma16816(float* d, const uint32_t* a, const uint32_t* b) {
    asm volatile(
        "mma.sync.aligned.m16n8k16.row.col.f32.bf16.bf16.f32 "
        "{%0,%1,%2,%3}, {%4,%5,%6,%7}, {%8,%9}, {%0,%1,%2,%3};"
        : "+f"(d[0]), "+f"(d[1]), "+f"(d[2]), "+f"(d[3])
        : "r"(a[0]), "r"(a[1]), "r"(a[2]), "r"(a[3]), "r"(b[0]), "r"(b[1]));
}
__device__ __forceinline__ void ldsm_x4(uint32_t* r, uint32_t addr) {
    asm volatile("ldmatrix.sync.aligned.m8n8.x4.shared.b16 {%0,%1,%2,%3}, [%4];"
        : "=r"(r[0]), "=r"(r[1]), "=r"(r[2]), "=r"(r[3]) : "r"(addr));
}

// ---------------- dtype probe + clear deg ----------------
__global__ void k_probe_clear(const int* __restrict__ ei32) {
    int i = blockIdx.x * blockDim.x + threadIdx.x;
    if (i < NNODES) g_deg[i] = 0;
    if (i == 0) {
        int allzero = 1;
#pragma unroll
        for (int j = 0; j < 8; j++) allzero &= (ei32[2 * j + 1] == 0);
        g_i64flag = allzero;
    }
}

// ---------------- CSR build ----------------
__global__ void k_count(const void* __restrict__ ei) {
    int i = blockIdx.x * blockDim.x + threadIdx.x;
    if (i >= ETOT) return;
    int s, d;
    if (i < NEDG) {
        if (g_i64flag) {
            const long long* p = (const long long*)ei;
            s = (int)p[i]; d = (int)p[NEDG + i];
        } else {
            const int* p = (const int*)ei;
            s = p[i]; d = p[NEDG + i];
        }
    } else {
        s = i - NEDG; d = s;
    }
    g_srcE[i] = s;
    g_dst[i] = d;
    atomicAdd(&g_deg[d], 1);
}

__global__ __launch_bounds__(1024) void k_scan_blk() {
    __shared__ int wsum[32];
    int tid = threadIdx.x, lane = tid & 31, w = tid >> 5;
    int i = blockIdx.x * 1024 + tid;
    int v = (i < NNODES) ? g_deg[i] : 0;
    int x = v;
#pragma unroll
    for (int o = 1; o < 32; o <<= 1) {
        int t = __shfl_up_sync(0xffffffffu, x, o);
        if (lane >= o) x += t;
    }
    if (lane == 31) wsum[w] = x;
    __syncthreads();
    if (w == 0) {
        int s = wsum[lane];
#pragma unroll
        for (int o = 1; o < 32; o <<= 1) {
            int t = __shfl_up_sync(0xffffffffu, s, o);
            if (lane >= o) s += t;
        }
        wsum[lane] = s;
    }
    __syncthreads();
    int incl = x + (w ? wsum[w - 1] : 0);
    if (i < NNODES) g_incl[i] = incl;
    if (tid == 1023) g_bsum[blockIdx.x] = incl;
}

__global__ void k_scan_top(int nb) {
    if (threadIdx.x == 0) {
        int acc = 0;
        for (int b = 0; b < nb; b++) { g_boff[b] = acc; acc += g_bsum[b]; }
    }
}

__global__ void k_scan_fix() {
    int i = blockIdx.x * blockDim.x + threadIdx.x;
    if (i >= NNODES) return;
    int incl = g_incl[i] + g_boff[i >> 10];
    g_rowptr[i + 1] = incl;
    g_cursor[i] = incl - g_deg[i];
    if (i == 0) g_rowptr[0] = 0;
}

__global__ void k_fill() {
    int i = blockIdx.x * blockDim.x + threadIdx.x;
    if (i >= ETOT) return;
    int p = atomicAdd(&g_cursor[g_dst[i]], 1);
    g_scsr[p] = g_srcE[i];
}

// ---------------- fp32 -> bf16 hi/lo (layer 0; also zeroes g_als/ald) -------
__global__ void k_splitA(const float* __restrict__ in, int n4) {
    int i = blockIdx.x * blockDim.x + threadIdx.x;
    if (i < NNODES) {
        float4 z = make_float4(0.f, 0.f, 0.f, 0.f);
        ((float4*)g_als)[i] = z;
        ((float4*)g_ald)[i] = z;
    }
    if (i >= n4) return;
    float4 v = *(const float4*)(in + (size_t)i * 4);
    __nv_bfloat16 hx = __float2bfloat16(v.x), hy = __float2bfloat16(v.y);
    __nv_bfloat16 hz = __float2bfloat16(v.z), hw = __float2bfloat16(v.w);
    __nv_bfloat16 lx = __float2bfloat16(v.x - __bfloat162float(hx));
    __nv_bfloat16 ly = __float2bfloat16(v.y - __bfloat162float(hy));
    __nv_bfloat16 lz = __float2bfloat16(v.z - __bfloat162float(hz));
    __nv_bfloat16 lw = __float2bfloat16(v.w - __bfloat162float(hw));
    __nv_bfloat162* ph = (__nv_bfloat162*)g_Ahi + (size_t)i * 2;
    __nv_bfloat162* pl = (__nv_bfloat162*)g_Alo + (size_t)i * 2;
    ph[0] = __nv_bfloat162(hx, hy); ph[1] = __nv_bfloat162(hz, hw);
    pl[0] = __nv_bfloat162(lx, ly); pl[1] = __nv_bfloat162(lz, lw);
}

// W split for layers 1/2 — also clears g_als/g_ald for the next fused GEMM
__global__ void k_splitW(const float* __restrict__ W, int K) {
    int i = blockIdx.x * blockDim.x + threadIdx.x;
    if (i < NNODES) {
        float4 z = make_float4(0.f, 0.f, 0.f, 0.f);
        ((float4*)g_als)[i] = z;
        ((float4*)g_ald)[i] = z;
    }
    if (i >= K * WID) return;
    int k = i >> 8, n = i & 255;
    float v = W[i];
    __nv_bfloat16 h = __float2bfloat16(v);
    __nv_bfloat16 l = __float2bfloat16(v - __bfloat162float(h));
    g_Bhi[n * K + k] = h;
    g_Blo[n * K + k] = l;
}

// W split for layer 0 (no clear — splitA does it)
__global__ void k_splitW0(const float* __restrict__ W, int K) {
    int i = blockIdx.x * blockDim.x + threadIdx.x;
    if (i >= K * WID) return;
    int k = i >> 8, n = i & 255;
    float v = W[i];
    __nv_bfloat16 h = __float2bfloat16(v);
    __nv_bfloat16 l = __float2bfloat16(v - __bfloat162float(h));
    g_Bhi[n * K + k] = h;
    g_Blo[n * K + k] = l;
}

// ---------------- HMMA GEMM + fused attention epilogue ----------------
#define ROWB2  80
#define OFF_AH 0
#define OFF_AL 10240
#define OFF_BH 20480
#define OFF_BL 30720
#define STG2   40960
#define GSMEM2 81920

__device__ __forceinline__ void load_stage2(uint32_t sb, int bm, int bn, int K,
                                            int k0, int tid) {
#pragma unroll
    for (int i = 0; i < 2; i++) {
        int idx = tid + i * 256;
        int row = idx >> 2, seg = idx & 3;
        uint32_t so = row * ROWB2 + seg * 16;
        size_t ga = (size_t)(bm + row) * K + k0 + seg * 8;
        size_t gb = (size_t)(bn + row) * K + k0 + seg * 8;
        cp16(sb + OFF_AH + so, g_Ahi + ga);
        cp16(sb + OFF_AL + so, g_Alo + ga);
        cp16(sb + OFF_BH + so, g_Bhi + gb);
        cp16(sb + OFF_BL + so, g_Blo + gb);
    }
}

__global__ __launch_bounds__(256, 2) void k_gemm_mma(int K,
        const float* __restrict__ asrc, const float* __restrict__ adst) {
    extern __shared__ char smem[];
    uint32_t sb = smem_u32(smem);
    int tid = threadIdx.x, lane = tid & 31, w = tid >> 5;
    int bm = blockIdx.x * 128, bn = blockIdx.y * 128;
    int wm = (w >> 2) * 64, wn = (w & 3) * 32;

    float acc[4][4][4];
#pragma unroll
    for (int mt = 0; mt < 4; mt++)
#pragma unroll
        for (int nt = 0; nt < 4; nt++)
#pragma unroll
            for (int j = 0; j < 4; j++) acc[mt][nt][j] = 0.f;

    uint32_t aoff = (uint32_t)(wm + (lane & 15)) * ROWB2 + (lane >> 4) * 16;
    uint32_t boff = (uint32_t)(wn + ((lane >> 4) & 1) * 8 + (lane & 7)) * ROWB2
                  + ((lane >> 3) & 1) * 16;

    const int nc = K >> 5;
    load_stage2(sb, bm, bn, K, 0, tid);
    CP_COMMIT();

    for (int kc = 0; kc < nc; kc++) {
        if (kc + 1 < nc) {
            load_stage2(sb + ((kc + 1) & 1) * STG2, bm, bn, K, (kc + 1) << 5, tid);
            CP_COMMIT();
            CP_WAIT(1);
        } else {
            CP_WAIT(0);
        }
        __syncthreads();
        uint32_t st = sb + (kc & 1) * STG2;
#pragma unroll
        for (int ks = 0; ks < 2; ks++) {
            uint32_t kb = ks * 32;
            uint32_t ah[4][4], al[4][4];
#pragma unroll
            for (int mt = 0; mt < 4; mt++) {
                ldsm_x4(ah[mt], st + OFF_AH + aoff + mt * 16 * ROWB2 + kb);
                ldsm_x4(al[mt], st + OFF_AL + aoff + mt * 16 * ROWB2 + kb);
            }
#pragma unroll
            for (int p = 0; p < 2; p++) {
                uint32_t bh[4], bl[4];
                ldsm_x4(bh, st + OFF_BH + boff + p * 16 * ROWB2 + kb);
                ldsm_x4(bl, st + OFF_BL + boff + p * 16 * ROWB2 + kb);
#pragma unroll
                for (int q = 0; q < 2; q++) {
                    int nt = p * 2 + q;
#pragma unroll
                    for (int mt = 0; mt < 4; mt++) {
                        mma16816(acc[mt][nt], ah[mt], bh + q * 2);
                        mma16816(acc[mt][nt], ah[mt], bl + q * 2);
                        mma16816(acc[mt][nt], al[mt], bh + q * 2);
                    }
                }
            }
        }
        __syncthreads();
    }

    // ---- fused epilogue: store g_h tile + per-row attention partial dots ---
    int r = lane >> 2, cq = lane & 3;
    int hh = ((bn + wn) >> 6) & 3;
    float2 as2[4], ad2[4];
#pragma unroll
    for (int nt = 0; nt < 4; nt++) {
        int col = bn + wn + nt * 8 + cq * 2;
        as2[nt] = *(const float2*)(asrc + col);
        ad2[nt] = *(const float2*)(adst + col);
    }
#pragma unroll
    for (int mt = 0; mt < 4; mt++) {
        int row0 = bm + wm + mt * 16 + r;
        float ps0 = 0.f, pd0 = 0.f, ps1 = 0.f, pd1 = 0.f;
#pragma unroll
        for (int nt = 0; nt < 4; nt++) {
            int col = bn + wn + nt * 8 + cq * 2;
            ps0 += acc[mt][nt][0] * as2[nt].x + acc[mt][nt][1] * as2[nt].y;
            pd0 += acc[mt][nt][0] * ad2[nt].x + acc[mt][nt][1] * ad2[nt].y;
            ps1 += acc[mt][nt][2] * as2[nt].x + acc[mt][nt][3] * as2[nt].y;
            pd1 += acc[mt][nt][2] * ad2[nt].x + acc[mt][nt][3] * ad2[nt].y;
            if (row0 < NNODES)
                *(float2*)(g_h + (size_t)row0 * WID + col) =
                    make_float2(acc[mt][nt][0], acc[mt][nt][1]);
            if (row0 + 8 < NNODES)
                *(float2*)(g_h + (size_t)(row0 + 8) * WID + col) =
                    make_float2(acc[mt][nt][2], acc[mt][nt][3]);
        }
        ps0 += __shfl_down_sync(0xffffffffu, ps0, 2);
        ps0 += __shfl_down_sync(0xffffffffu, ps0, 1);
        pd0 += __shfl_down_sync(0xffffffffu, pd0, 2);
        pd0 += __shfl_down_sync(0xffffffffu, pd0, 1);
        ps1 += __shfl_down_sync(0xffffffffu, ps1, 2);
        ps1 += __shfl_down_sync(0xffffffffu, ps1, 1);
        pd1 += __shfl_down_sync(0xffffffffu, pd1, 2);
        pd1 += __shfl_down_sync(0xffffffffu, pd1, 1);
        if (cq == 0) {
            if (row0 < NNODES) {
                atomicAdd(&g_als[row0 * 4 + hh], ps0);
                atomicAdd(&g_ald[row0 * 4 + hh], pd0);
            }
            if (row0 + 8 < NNODES) {
                atomicAdd(&g_als[(row0 + 8) * 4 + hh], ps1);
                atomicAdd(&g_ald[(row0 + 8) * 4 + hh], pd1);
            }
        }
    }
}

// --------- per-node softmax + aggregate + bias + ELU (smem-staged, MLP4) ----
__global__ __launch_bounds__(128) void k_aggregate(const float* __restrict__ bias, int dosplit) {
    __shared__ int   sh_src[DCAP];
    __shared__ float sh_al[4][DCAP];
    __shared__ float s_inv[4];
    int n = blockIdx.x;
    int tid = threadIdx.x, lane = tid & 31, w = tid >> 5;
    int start = g_rowptr[n];
    int deg = g_rowptr[n + 1] - start;

    if (deg <= DCAP) {
        for (int i = tid; i < deg; i += 128) {
            int s = g_scsr[start + i];
            sh_src[i] = s;
            float4 a = ((const float4*)g_als)[s];
            sh_al[0][i] = a.x; sh_al[1][i] = a.y;
            sh_al[2][i] = a.z; sh_al[3][i] = a.w;
        }
        __syncthreads();

        float aldn = g_ald[n * 4 + w];
        float mx = -1e30f;
        for (int i = lane; i < deg; i += 32) {
            float v = sh_al[w][i] + aldn;
            v = v > 0.f ? v : 0.2f * v;
            sh_al[w][i] = v;
            mx = fmaxf(mx, v);
        }
#pragma unroll
        for (int o = 16; o; o >>= 1) mx = fmaxf(mx, __shfl_xor_sync(0xffffffffu, mx, o));
        float sum = 0.f;
        for (int i = lane; i < deg; i += 32) {
            float ex = expf(sh_al[w][i] - mx);
            sh_al[w][i] = ex;
            sum += ex;
        }
#pragma unroll
        for (int o = 16; o; o >>= 1) sum += __shfl_xor_sync(0xffffffffu, sum, o);
        if (lane == 0) s_inv[w] = 1.f / (sum + 1e-16f);
        __syncthreads();

        // aggregate: 4 independent accumulator chains (MLP=4)
        const float* alp = sh_al[w];
        float2 A0 = make_float2(0.f, 0.f), A1 = A0, A2 = A0, A3 = A0;
        int i = 0;
        for (; i + 4 <= deg; i += 4) {
            float p0 = alp[i], p1 = alp[i + 1], p2 = alp[i + 2], p3 = alp[i + 3];
            float2 u0 = *((const float2*)(g_h + (size_t)sh_src[i]     * WID) + tid);
            float2 u1 = *((const float2*)(g_h + (size_t)sh_src[i + 1] * WID) + tid);
            float2 u2 = *((const float2*)(g_h + (size_t)sh_src[i + 2] * WID) + tid);
            float2 u3 = *((const float2*)(g_h + (size_t)sh_src[i + 3] * WID) + tid);
            A0.x += p0 * u0.x; A0.y += p0 * u0.y;
            A1.x += p1 * u1.x; A1.y += p1 * u1.y;
            A2.x += p2 * u2.x; A2.y += p2 * u2.y;
            A3.x += p3 * u3.x; A3.y += p3 * u3.y;
        }
        for (; i < deg; i++) {
            float p = alp[i];
            float2 u = *((const float2*)(g_h + (size_t)sh_src[i] * WID) + tid);
            A0.x += p * u.x; A0.y += p * u.y;
        }
        float inv = s_inv[w];
        int c = tid * 2;
        float v0 = ((A0.x + A1.x) + (A2.x + A3.x)) * inv + bias[c];
        float v1 = ((A0.y + A1.y) + (A2.y + A3.y)) * inv + bias[c + 1];
        v0 = v0 > 0.f ? v0 : expm1f(v0);
        v1 = v1 > 0.f ? v1 : expm1f(v1);
        if (dosplit) {
            __nv_bfloat16 H0 = __float2bfloat16(v0), H1 = __float2bfloat16(v1);
            *((__nv_bfloat162*)(g_Ahi + (size_t)n * WID + c)) = __nv_bfloat162(H0, H1);
            *((__nv_bfloat162*)(g_Alo + (size_t)n * WID + c)) =
                __nv_bfloat162(__float2bfloat16(v0 - __bfloat162float(H0)),
                               __float2bfloat16(v1 - __bfloat162float(H1)));
        } else {
            *((float2*)(g_featA + (size_t)n * WID + c)) = make_float2(v0, v1);
        }
        return;
    }

    // -------- fallback: deg > DCAP ----------
    {
        float aldn = g_ald[n * 4 + w];
        float mx = -1e30f;
        for (int i = lane; i < deg; i += 32) {
            float v = g_als[g_scsr[start + i] * 4 + w] + aldn;
            v = v > 0.f ? v : 0.2f * v;
            g_esc[(size_t)(start + i) * 4 + w] = v;
            mx = fmaxf(mx, v);
        }
#pragma unroll
        for (int o = 16; o; o >>= 1) mx = fmaxf(mx, __shfl_xor_sync(0xffffffffu, mx, o));
        float sum = 0.f;
        for (int i = lane; i < deg; i += 32) {
            float ex = expf(g_esc[(size_t)(start + i) * 4 + w] - mx);
            g_esc[(size_t)(start + i) * 4 + w] = ex;
            sum += ex;
        }
#pragma unroll
        for (int o = 16; o; o >>= 1) sum += __shfl_xor_sync(0xffffffffu, sum, o);
        if (lane == 0) s_inv[w] = 1.f / (sum + 1e-16f);
    }
    __syncthreads();
    {
        float2 acc = make_float2(0.f, 0.f);
        for (int i = 0; i < deg; i++) {
            int s = g_scsr[start + i];
            float a = g_esc[(size_t)(start + i) * 4 + w];
            float2 v = *((const float2*)(g_h + (size_t)s * WID) + tid);
            acc.x += a * v.x;
            acc.y += a * v.y;
        }
        float inv = s_inv[w];
        int c = tid * 2;
        float v0 = acc.x * inv + bias[c];
        float v1 = acc.y * inv + bias[c + 1];
        v0 = v0 > 0.f ? v0 : expm1f(v0);
        v1 = v1 > 0.f ? v1 : expm1f(v1);
        if (dosplit) {
            __nv_bfloat16 H0 = __float2bfloat16(v0), H1 = __float2bfloat16(v1);
            *((__nv_bfloat162*)(g_Ahi + (size_t)n * WID + c)) = __nv_bfloat162(H0, H1);
            *((__nv_bfloat162*)(g_Alo + (size_t)n * WID + c)) =
                __nv_bfloat162(__float2bfloat16(v0 - __bfloat162float(H0)),
                               __float2bfloat16(v1 - __bfloat162float(H1)));
        } else {
            *((float2*)(g_featA + (size_t)n * WID + c)) = make_float2(v0, v1);
        }
    }
}

// ---------------- pooling + final linear ----------------
__global__ void k_init_out(float* out, const float* __restrict__ lin_b) {
    int i = threadIdx.x;
    if (i < NG) out[i] = lin_b[0];
}

__global__ void k_pool(const float* __restrict__ linw,
                       const void* __restrict__ batch, float* out) {
    int gw = (blockIdx.x * blockDim.x + threadIdx.x) >> 5;
    int lane = threadIdx.x & 31;
    if (gw >= NNODES) return;
    const float* f = g_featA + (size_t)gw * WID + lane * 8;
    float4 a  = *(const float4*)(f);
    float4 b  = *(const float4*)(f + 4);
    float4 wa = *(const float4*)(linw + lane * 8);
    float4 wb = *(const float4*)(linw + lane * 8 + 4);
    float s = a.x * wa.x + a.y * wa.y + a.z * wa.z + a.w * wa.w
            + b.x * wb.x + b.y * wb.y + b.z * wb.z + b.w * wb.w;
#pragma unroll
    for (int o = 16; o; o >>= 1) s += __shfl_xor_sync(0xffffffffu, s, o);
    if (lane == 0) {
        int g = g_i64flag ? (int)((const long long*)batch)[gw]
                          : ((const int*)batch)[gw];
        atomicAdd(&out[g], s);
    }
}

// ---------------- launch ----------------
extern "C" void kernel_launch(void* const* d_in, const int* in_sizes, int n_in,
                              void* d_out, int out_size) {
    const float* x     = (const float*)d_in[0];
    const void*  ei    = d_in[1];
    const void*  batch = d_in[3];
    const float* W[3]    = {(const float*)d_in[4],  (const float*)d_in[8],  (const float*)d_in[12]};
    const float* asrc[3] = {(const float*)d_in[5],  (const float*)d_in[9],  (const float*)d_in[13]};
    const float* adst[3] = {(const float*)d_in[6],  (const float*)d_in[10], (const float*)d_in[14]};
    const float* bb[3]   = {(const float*)d_in[7],  (const float*)d_in[11], (const float*)d_in[15]};
    const float* linw = (const float*)d_in[16];
    const float* linb = (const float*)d_in[17];
    float* out = (float*)d_out;

    static int smem_set = 0;
    if (!smem_set) {
        cudaFuncSetAttribute(k_gemm_mma, cudaFuncAttributeMaxDynamicSharedMemorySize, GSMEM2);
        smem_set = 1;
    }

    int warpGrid = (NNODES * 32 + 255) / 256;
    dim3 ggrid(MTILES, 2);
    int nodeGrid = (NNODES + 255) / 256;

    // probe + clear, layer-0 split (also zeroes g_als/ald), W0 split, GEMM0
    k_probe_clear<<<nodeGrid, 256>>>((const int*)ei);
    k_splitA<<<(NNODES * 128 / 4 + 255) / 256, 256>>>(x, NNODES * 128 / 4);
    k_splitW0<<<(128 * WID + 255) / 256, 256>>>(W[0], 128);
    k_gemm_mma<<<ggrid, 256, GSMEM2>>>(128, asrc[0], adst[0]);

    // CSR build (before first aggregate)
    k_count<<<(ETOT + 255) / 256, 256>>>(ei);
    int nb = (NNODES + 1023) / 1024;
    k_scan_blk<<<nb, 1024>>>();
    k_scan_top<<<1, 32>>>(nb);
    k_scan_fix<<<nodeGrid, 256>>>();
    k_fill<<<(ETOT + 255) / 256, 256>>>();

    // layer 0 tail
    k_aggregate<<<NNODES, 128>>>(bb[0], 1);

    // layer 1 (K=256); splitW also clears g_als/ald
    k_splitW<<<(256 * WID + 255) / 256, 256>>>(W[1], 256);
    k_gemm_mma<<<ggrid, 256, GSMEM2>>>(256, asrc[1], adst[1]);
    k_aggregate<<<NNODES, 128>>>(bb[1], 1);

    // layer 2 (K=256)
    k_splitW<<<(256 * WID + 255) / 256, 256>>>(W[2], 256);
    k_gemm_mma<<<ggrid, 256, GSMEM2>>>(256, asrc[2], adst[2]);
    k_aggregate<<<NNODES, 128>>>(bb[2], 0);

    // pooling + head
    k_init_out<<<1, 256>>>(out, linb);
    k_pool<<<warpGrid, 256>>>(linw, batch, out);
}

// round 9
// speedup vs baseline: 1.0387x; 1.0387x over previous
#include <cuda_runtime.h>
#include <cuda_bf16.h>
#include <math.h>
#include <stdint.h>

#define NNODES 50000
#define NEDG   400000
#define ETOT   450000
#define WID    256
#define NG     256
#define NPAD   50048        // 391 * 128
#define MTILES 391
#define DCAP   256

// ---------------- scratch globals ----------------
__device__ float g_h[(size_t)NNODES * WID];
__device__ float g_als[NNODES * 4];
__device__ float g_ald[NNODES * 4];
__device__ float g_esc[(size_t)ETOT * 4];    // fallback only (deg > DCAP)
__device__ int   g_dst[ETOT];
__device__ int   g_srcE[ETOT];
__device__ int   g_scsr[ETOT];
__device__ int   g_deg[NNODES];
__device__ int   g_rowptr[NNODES + 1];
__device__ int   g_cursor[NNODES];
__device__ int   g_i64flag;
__device__ int   g_incl[NNODES];
__device__ int   g_bsum[64];
__device__ int   g_boff[64];
// bf16 split operands (zero-init covers M padding)
__device__ __align__(16) __nv_bfloat16 g_Ahi[(size_t)NPAD * WID];
__device__ __align__(16) __nv_bfloat16 g_Alo[(size_t)NPAD * WID];
__device__ __align__(16) __nv_bfloat16 g_Bhi[WID * WID];   // [N=256][K]
__device__ __align__(16) __nv_bfloat16 g_Blo[WID * WID];

// ---------------- helpers ----------------
__device__ __forceinline__ uint32_t smem_u32(const void* p) {
    uint32_t a;
    asm("{ .reg .u64 t; cvta.to.shared.u64 t, %1; cvt.u32.u64 %0, t; }" : "=r"(a) : "l"(p));
    return a;
}
__device__ __forceinline__ void cp16(uint32_t s, const void* g) {
    asm volatile("cp.async.cg.shared.global [%0], [%1], 16;" :: "r"(s), "l"(g));
}
#define CP_COMMIT()  asm volatile("cp.async.commit_group;" ::: "memory")
#define CP_WAIT(n)   asm volatile("cp.async.wait_group %0;" :: "n"(n) : "memory")

__device__ __forceinline__ void mma16816(float* d, const uint32_t* a, const uint32_t* b) {
    asm volatile(
        "mma.sync.aligned.m16n8k16.row.col.f32.bf16.bf16.f32 "
        "{%0,%1,%2,%3}, {%4,%5,%6,%7}, {%8,%9}, {%0,%1,%2,%3};"
        : "+f"(d[0]), "+f"(d[1]), "+f"(d[2]), "+f"(d[3])
        : "r"(a[0]), "r"(a[1]), "r"(a[2]), "r"(a[3]), "r"(b[0]), "r"(b[1]));
}
__device__ __forceinline__ void ldsm_x4(uint32_t* r, uint32_t addr) {
    asm volatile("ldmatrix.sync.aligned.m8n8.x4.shared.b16 {%0,%1,%2,%3}, [%4];"
        : "=r"(r[0]), "=r"(r[1]), "=r"(r[2]), "=r"(r[3]) : "r"(addr));
}

// ---------------- dtype probe + clear deg ----------------
__global__ void k_probe_clear(const int* __restrict__ ei32) {
    int i = blockIdx.x * blockDim.x + threadIdx.x;
    if (i < NNODES) g_deg[i] = 0;
    if (i == 0) {
        int allzero = 1;
#pragma unroll
        for (int j = 0; j < 8; j++) allzero &= (ei32[2 * j + 1] == 0);
        g_i64flag = allzero;
    }
}

// ---------------- CSR build ----------------
__global__ void k_count(const void* __restrict__ ei) {
    int i = blockIdx.x * blockDim.x + threadIdx.x;
    if (i >= ETOT) return;
    int s, d;
    if (i < NEDG) {
        if (g_i64flag) {
            const long long* p = (const long long*)ei;
            s = (int)p[i]; d = (int)p[NEDG + i];
        } else {
            const int* p = (const int*)ei;
            s = p[i]; d = p[NEDG + i];
        }
    } else {
        s = i - NEDG; d = s;
    }
    g_srcE[i] = s;
    g_dst[i] = d;
    atomicAdd(&g_deg[d], 1);
}

__global__ __launch_bounds__(1024) void k_scan_blk() {
    __shared__ int wsum[32];
    int tid = threadIdx.x, lane = tid & 31, w = tid >> 5;
    int i = blockIdx.x * 1024 + tid;
    int v = (i < NNODES) ? g_deg[i] : 0;
    int x = v;
#pragma unroll
    for (int o = 1; o < 32; o <<= 1) {
        int t = __shfl_up_sync(0xffffffffu, x, o);
        if (lane >= o) x += t;
    }
    if (lane == 31) wsum[w] = x;
    __syncthreads();
    if (w == 0) {
        int s = wsum[lane];
#pragma unroll
        for (int o = 1; o < 32; o <<= 1) {
            int t = __shfl_up_sync(0xffffffffu, s, o);
            if (lane >= o) s += t;
        }
        wsum[lane] = s;
    }
    __syncthreads();
    int incl = x + (w ? wsum[w - 1] : 0);
    if (i < NNODES) g_incl[i] = incl;
    if (tid == 1023) g_bsum[blockIdx.x] = incl;
}

__global__ void k_scan_top(int nb) {
    if (threadIdx.x == 0) {
        int acc = 0;
        for (int b = 0; b < nb; b++) { g_boff[b] = acc; acc += g_bsum[b]; }
    }
}

__global__ void k_scan_fix() {
    int i = blockIdx.x * blockDim.x + threadIdx.x;
    if (i >= NNODES) return;
    int incl = g_incl[i] + g_boff[i >> 10];
    g_rowptr[i + 1] = incl;
    g_cursor[i] = incl - g_deg[i];
    if (i == 0) g_rowptr[0] = 0;
}

__global__ void k_fill() {
    int i = blockIdx.x * blockDim.x + threadIdx.x;
    if (i >= ETOT) return;
    int p = atomicAdd(&g_cursor[g_dst[i]], 1);
    g_scsr[p] = g_srcE[i];
}

// ---------------- fp32 -> bf16 hi/lo (layer 0; also zeroes g_als/ald) -------
__global__ void k_splitA(const float* __restrict__ in, int n4) {
    int i = blockIdx.x * blockDim.x + threadIdx.x;
    if (i < NNODES) {
        float4 z = make_float4(0.f, 0.f, 0.f, 0.f);
        ((float4*)g_als)[i] = z;
        ((float4*)g_ald)[i] = z;
    }
    if (i >= n4) return;
    float4 v = *(const float4*)(in + (size_t)i * 4);
    __nv_bfloat16 hx = __float2bfloat16(v.x), hy = __float2bfloat16(v.y);
    __nv_bfloat16 hz = __float2bfloat16(v.z), hw = __float2bfloat16(v.w);
    __nv_bfloat16 lx = __float2bfloat16(v.x - __bfloat162float(hx));
    __nv_bfloat16 ly = __float2bfloat16(v.y - __bfloat162float(hy));
    __nv_bfloat16 lz = __float2bfloat16(v.z - __bfloat162float(hz));
    __nv_bfloat16 lw = __float2bfloat16(v.w - __bfloat162float(hw));
    __nv_bfloat162* ph = (__nv_bfloat162*)g_Ahi + (size_t)i * 2;
    __nv_bfloat162* pl = (__nv_bfloat162*)g_Alo + (size_t)i * 2;
    ph[0] = __nv_bfloat162(hx, hy); ph[1] = __nv_bfloat162(hz, hw);
    pl[0] = __nv_bfloat162(lx, ly); pl[1] = __nv_bfloat162(lz, lw);
}

// W split for layers 1/2 — also clears g_als/g_ald for the next fused GEMM
__global__ void k_splitW(const float* __restrict__ W, int K) {
    int i = blockIdx.x * blockDim.x + threadIdx.x;
    if (i < NNODES) {
        float4 z = make_float4(0.f, 0.f, 0.f, 0.f);
        ((float4*)g_als)[i] = z;
        ((float4*)g_ald)[i] = z;
    }
    if (i >= K * WID) return;
    int k = i >> 8, n = i & 255;
    float v = W[i];
    __nv_bfloat16 h = __float2bfloat16(v);
    __nv_bfloat16 l = __float2bfloat16(v - __bfloat162float(h));
    g_Bhi[n * K + k] = h;
    g_Blo[n * K + k] = l;
}

// W split for layer 0 (no clear — splitA does it)
__global__ void k_splitW0(const float* __restrict__ W, int K) {
    int i = blockIdx.x * blockDim.x + threadIdx.x;
    if (i >= K * WID) return;
    int k = i >> 8, n = i & 255;
    float v = W[i];
    __nv_bfloat16 h = __float2bfloat16(v);
    __nv_bfloat16 l = __float2bfloat16(v - __bfloat162float(h));
    g_Bhi[n * K + k] = h;
    g_Blo[n * K + k] = l;
}

// ---------------- HMMA GEMM + fused attention epilogue ----------------
#define ROWB2  80
#define OFF_AH 0
#define OFF_AL 10240
#define OFF_BH 20480
#define OFF_BL 30720
#define STG2   40960
#define GSMEM2 81920

__device__ __forceinline__ void load_stage2(uint32_t sb, int bm, int bn, int K,
                                            int k0, int tid) {
#pragma unroll
    for (int i = 0; i < 2; i++) {
        int idx = tid + i * 256;
        int row = idx >> 2, seg = idx & 3;
        uint32_t so = row * ROWB2 + seg * 16;
        size_t ga = (size_t)(bm + row) * K + k0 + seg * 8;
        size_t gb = (size_t)(bn + row) * K + k0 + seg * 8;
        cp16(sb + OFF_AH + so, g_Ahi + ga);
        cp16(sb + OFF_AL + so, g_Alo + ga);
        cp16(sb + OFF_BH + so, g_Bhi + gb);
        cp16(sb + OFF_BL + so, g_Blo + gb);
    }
}

__global__ __launch_bounds__(256, 2) void k_gemm_mma(int K,
        const float* __restrict__ asrc, const float* __restrict__ adst) {
    extern __shared__ char smem[];
    uint32_t sb = smem_u32(smem);
    int tid = threadIdx.x, lane = tid & 31, w = tid >> 5;
    int bm = blockIdx.x * 128, bn = blockIdx.y * 128;
    int wm = (w >> 2) * 64, wn = (w & 3) * 32;

    float acc[4][4][4];
#pragma unroll
    for (int mt = 0; mt < 4; mt++)
#pragma unroll
        for (int nt = 0; nt < 4; nt++)
#pragma unroll
            for (int j = 0; j < 4; j++) acc[mt][nt][j] = 0.f;

    uint32_t aoff = (uint32_t)(wm + (lane & 15)) * ROWB2 + (lane >> 4) * 16;
    uint32_t boff = (uint32_t)(wn + ((lane >> 4) & 1) * 8 + (lane & 7)) * ROWB2
                  + ((lane >> 3) & 1) * 16;

    const int nc = K >> 5;
    load_stage2(sb, bm, bn, K, 0, tid);
    CP_COMMIT();

    for (int kc = 0; kc < nc; kc++) {
        if (kc + 1 < nc) {
            load_stage2(sb + ((kc + 1) & 1) * STG2, bm, bn, K, (kc + 1) << 5, tid);
            CP_COMMIT();
            CP_WAIT(1);
        } else {
            CP_WAIT(0);
        }
        __syncthreads();
        uint32_t st = sb + (kc & 1) * STG2;
#pragma unroll
        for (int ks = 0; ks < 2; ks++) {
            uint32_t kb = ks * 32;
            uint32_t ah[4][4], al[4][4];
#pragma unroll
            for (int mt = 0; mt < 4; mt++) {
                ldsm_x4(ah[mt], st + OFF_AH + aoff + mt * 16 * ROWB2 + kb);
                ldsm_x4(al[mt], st + OFF_AL + aoff + mt * 16 * ROWB2 + kb);
            }
#pragma unroll
            for (int p = 0; p < 2; p++) {
                uint32_t bh[4], bl[4];
                ldsm_x4(bh, st + OFF_BH + boff + p * 16 * ROWB2 + kb);
                ldsm_x4(bl, st + OFF_BL + boff + p * 16 * ROWB2 + kb);
#pragma unroll
                for (int q = 0; q < 2; q++) {
                    int nt = p * 2 + q;
#pragma unroll
                    for (int mt = 0; mt < 4; mt++) {
                        mma16816(acc[mt][nt], ah[mt], bh + q * 2);
                        mma16816(acc[mt][nt], ah[mt], bl + q * 2);
                        mma16816(acc[mt][nt], al[mt], bh + q * 2);
                    }
                }
            }
        }
        __syncthreads();
    }

    // ---- fused epilogue: store g_h tile + per-row attention partial dots ---
    int r = lane >> 2, cq = lane & 3;
    int hh = ((bn + wn) >> 6) & 3;
    float2 as2[4], ad2[4];
#pragma unroll
    for (int nt = 0; nt < 4; nt++) {
        int col = bn + wn + nt * 8 + cq * 2;
        as2[nt] = *(const float2*)(asrc + col);
        ad2[nt] = *(const float2*)(adst + col);
    }
#pragma unroll
    for (int mt = 0; mt < 4; mt++) {
        int row0 = bm + wm + mt * 16 + r;
        float ps0 = 0.f, pd0 = 0.f, ps1 = 0.f, pd1 = 0.f;
#pragma unroll
        for (int nt = 0; nt < 4; nt++) {
            int col = bn + wn + nt * 8 + cq * 2;
            ps0 += acc[mt][nt][0] * as2[nt].x + acc[mt][nt][1] * as2[nt].y;
            pd0 += acc[mt][nt][0] * ad2[nt].x + acc[mt][nt][1] * ad2[nt].y;
            ps1 += acc[mt][nt][2] * as2[nt].x + acc[mt][nt][3] * as2[nt].y;
            pd1 += acc[mt][nt][2] * ad2[nt].x + acc[mt][nt][3] * ad2[nt].y;
            if (row0 < NNODES)
                *(float2*)(g_h + (size_t)row0 * WID + col) =
                    make_float2(acc[mt][nt][0], acc[mt][nt][1]);
            if (row0 + 8 < NNODES)
                *(float2*)(g_h + (size_t)(row0 + 8) * WID + col) =
                    make_float2(acc[mt][nt][2], acc[mt][nt][3]);
        }
        ps0 += __shfl_down_sync(0xffffffffu, ps0, 2);
        ps0 += __shfl_down_sync(0xffffffffu, ps0, 1);
        pd0 += __shfl_down_sync(0xffffffffu, pd0, 2);
        pd0 += __shfl_down_sync(0xffffffffu, pd0, 1);
        ps1 += __shfl_down_sync(0xffffffffu, ps1, 2);
        ps1 += __shfl_down_sync(0xffffffffu, ps1, 1);
        pd1 += __shfl_down_sync(0xffffffffu, pd1, 2);
        pd1 += __shfl_down_sync(0xffffffffu, pd1, 1);
        if (cq == 0) {
            if (row0 < NNODES) {
                atomicAdd(&g_als[row0 * 4 + hh], ps0);
                atomicAdd(&g_ald[row0 * 4 + hh], pd0);
            }
            if (row0 + 8 < NNODES) {
                atomicAdd(&g_als[(row0 + 8) * 4 + hh], ps1);
                atomicAdd(&g_ald[(row0 + 8) * 4 + hh], pd1);
            }
        }
    }
}

// --------- per-node softmax + aggregate + bias + ELU ---------
// dosplit=1: write bf16 hi/lo for next GEMM.  dosplit=0: fused pool+linear.
__global__ __launch_bounds__(128) void k_aggregate(const float* __restrict__ bias, int dosplit,
        const float* __restrict__ linw, const void* __restrict__ batch, float* out) {
    __shared__ int   sh_src[DCAP];
    __shared__ float sh_al[4][DCAP];
    __shared__ float s_inv[4];
    __shared__ float s_red[4];
    int n = blockIdx.x;
    int tid = threadIdx.x, lane = tid & 31, w = tid >> 5;
    int start = g_rowptr[n];
    int deg = g_rowptr[n + 1] - start;

    float v0, v1;
    int c = tid * 2;

    if (deg <= DCAP) {
        for (int i = tid; i < deg; i += 128) {
            int s = g_scsr[start + i];
            sh_src[i] = s;
            float4 a = ((const float4*)g_als)[s];
            sh_al[0][i] = a.x; sh_al[1][i] = a.y;
            sh_al[2][i] = a.z; sh_al[3][i] = a.w;
        }
        __syncthreads();

        float aldn = g_ald[n * 4 + w];
        float mx = -1e30f;
        for (int i = lane; i < deg; i += 32) {
            float v = sh_al[w][i] + aldn;
            v = v > 0.f ? v : 0.2f * v;
            sh_al[w][i] = v;
            mx = fmaxf(mx, v);
        }
#pragma unroll
        for (int o = 16; o; o >>= 1) mx = fmaxf(mx, __shfl_xor_sync(0xffffffffu, mx, o));
        float sum = 0.f;
        for (int i = lane; i < deg; i += 32) {
            float ex = expf(sh_al[w][i] - mx);
            sh_al[w][i] = ex;
            sum += ex;
        }
#pragma unroll
        for (int o = 16; o; o >>= 1) sum += __shfl_xor_sync(0xffffffffu, sum, o);
        if (lane == 0) s_inv[w] = 1.f / (sum + 1e-16f);
        __syncthreads();

        // aggregate with dual accumulators (2 independent gather chains)
        const float* alp = sh_al[w];
        float2 a0 = make_float2(0.f, 0.f), a1 = make_float2(0.f, 0.f);
        int i = 0;
#pragma unroll 2
        for (; i + 2 <= deg; i += 2) {
            float p = alp[i], q = alp[i + 1];
            float2 u = *((const float2*)(g_h + (size_t)sh_src[i] * WID) + tid);
            float2 v = *((const float2*)(g_h + (size_t)sh_src[i + 1] * WID) + tid);
            a0.x += p * u.x; a0.y += p * u.y;
            a1.x += q * v.x; a1.y += q * v.y;
        }
        if (i < deg) {
            float p = alp[i];
            float2 u = *((const float2*)(g_h + (size_t)sh_src[i] * WID) + tid);
            a0.x += p * u.x; a0.y += p * u.y;
        }
        float inv = s_inv[w];
        v0 = (a0.x + a1.x) * inv + bias[c];
        v1 = (a0.y + a1.y) * inv + bias[c + 1];
    } else {
        // -------- fallback: deg > DCAP ----------
        float aldn = g_ald[n * 4 + w];
        float mx = -1e30f;
        for (int i = lane; i < deg; i += 32) {
            float v = g_als[g_scsr[start + i] * 4 + w] + aldn;
            v = v > 0.f ? v : 0.2f * v;
            g_esc[(size_t)(start + i) * 4 + w] = v;
            mx = fmaxf(mx, v);
        }
#pragma unroll
        for (int o = 16; o; o >>= 1) mx = fmaxf(mx, __shfl_xor_sync(0xffffffffu, mx, o));
        float sum = 0.f;
        for (int i = lane; i < deg; i += 32) {
            float ex = expf(g_esc[(size_t)(start + i) * 4 + w] - mx);
            g_esc[(size_t)(start + i) * 4 + w] = ex;
            sum += ex;
        }
#pragma unroll
        for (int o = 16; o; o >>= 1) sum += __shfl_xor_sync(0xffffffffu, sum, o);
        if (lane == 0) s_inv[w] = 1.f / (sum + 1e-16f);
        __syncthreads();

        float2 acc = make_float2(0.f, 0.f);
        for (int i = 0; i < deg; i++) {
            int s = g_scsr[start + i];
            float a = g_esc[(size_t)(start + i) * 4 + w];
            float2 v = *((const float2*)(g_h + (size_t)s * WID) + tid);
            acc.x += a * v.x;
            acc.y += a * v.y;
        }
        float inv = s_inv[w];
        v0 = acc.x * inv + bias[c];
        v1 = acc.y * inv + bias[c + 1];
    }

    v0 = v0 > 0.f ? v0 : expm1f(v0);           // ELU
    v1 = v1 > 0.f ? v1 : expm1f(v1);

    if (dosplit) {
        __nv_bfloat16 H0 = __float2bfloat16(v0), H1 = __float2bfloat16(v1);
        *((__nv_bfloat162*)(g_Ahi + (size_t)n * WID + c)) = __nv_bfloat162(H0, H1);
        *((__nv_bfloat162*)(g_Alo + (size_t)n * WID + c)) =
            __nv_bfloat162(__float2bfloat16(v0 - __bfloat162float(H0)),
                           __float2bfloat16(v1 - __bfloat162float(H1)));
    } else {
        // fused pooling + linear head: partial = v . lin_w, block reduce, atomic
        float part = v0 * linw[c] + v1 * linw[c + 1];
#pragma unroll
        for (int o = 16; o; o >>= 1) part += __shfl_xor_sync(0xffffffffu, part, o);
        if (lane == 0) s_red[w] = part;
        __syncthreads();
        if (tid == 0) {
            float tot = (s_red[0] + s_red[1]) + (s_red[2] + s_red[3]);
            int g = g_i64flag ? (int)((const long long*)batch)[n]
                              : ((const int*)batch)[n];
            atomicAdd(&out[g], tot);
        }
    }
}

// ---------------- out init ----------------
__global__ void k_init_out(float* out, const float* __restrict__ lin_b) {
    int i = threadIdx.x;
    if (i < NG) out[i] = lin_b[0];
}

// ---------------- launch ----------------
extern "C" void kernel_launch(void* const* d_in, const int* in_sizes, int n_in,
                              void* d_out, int out_size) {
    const float* x     = (const float*)d_in[0];
    const void*  ei    = d_in[1];
    const void*  batch = d_in[3];
    const float* W[3]    = {(const float*)d_in[4],  (const float*)d_in[8],  (const float*)d_in[12]};
    const float* asrc[3] = {(const float*)d_in[5],  (const float*)d_in[9],  (const float*)d_in[13]};
    const float* adst[3] = {(const float*)d_in[6],  (const float*)d_in[10], (const float*)d_in[14]};
    const float* bb[3]   = {(const float*)d_in[7],  (const float*)d_in[11], (const float*)d_in[15]};
    const float* linw = (const float*)d_in[16];
    const float* linb = (const float*)d_in[17];
    float* out = (float*)d_out;

    static int smem_set = 0;
    if (!smem_set) {
        cudaFuncSetAttribute(k_gemm_mma, cudaFuncAttributeMaxDynamicSharedMemorySize, GSMEM2);
        smem_set = 1;
    }

    dim3 ggrid(MTILES, 2);
    int nodeGrid = (NNODES + 255) / 256;

    // probe + clear, layer-0 split (also zeroes g_als/ald), W0 split, GEMM0
    k_probe_clear<<<nodeGrid, 256>>>((const int*)ei);
    k_splitA<<<(NNODES * 128 / 4 + 255) / 256, 256>>>(x, NNODES * 128 / 4);
    k_splitW0<<<(128 * WID + 255) / 256, 256>>>(W[0], 128);
    k_gemm_mma<<<ggrid, 256, GSMEM2>>>(128, asrc[0], adst[0]);

    // CSR build (before first aggregate)
    k_count<<<(ETOT + 255) / 256, 256>>>(ei);
    int nb = (NNODES + 1023) / 1024;
    k_scan_blk<<<nb, 1024>>>();
    k_scan_top<<<1, 32>>>(nb);
    k_scan_fix<<<nodeGrid, 256>>>();
    k_fill<<<(ETOT + 255) / 256, 256>>>();

    // layer 0 tail
    k_aggregate<<<NNODES, 128>>>(bb[0], 1, nullptr, nullptr, nullptr);

    // layer 1 (K=256); splitW also clears g_als/ald
    k_splitW<<<(256 * WID + 255) / 256, 256>>>(W[1], 256);
    k_gemm_mma<<<ggrid, 256, GSMEM2>>>(256, asrc[1], adst[1]);
    k_aggregate<<<NNODES, 128>>>(bb[1], 1, nullptr, nullptr, nullptr);

    // layer 2 (K=256): aggregate fuses pooling + linear head
    k_splitW<<<(256 * WID + 255) / 256, 256>>>(W[2], 256);
    k_gemm_mma<<<ggrid, 256, GSMEM2>>>(256, asrc[2], adst[2]);
    k_init_out<<<1, 256>>>(out, linb);
    k_aggregate<<<NNODES, 128>>>(bb[2], 0, linw, batch, out);
}

// round 10
// speedup vs baseline: 1.0570x; 1.0176x over previous
#include <cuda_runtime.h>
#include <cuda_bf16.h>
#include <math.h>
#include <stdint.h>

#define NNODES 50000
#define NEDG   400000
#define ETOT   450000
#define WID    256
#define NG     256
#define NPAD   50048        // 391 * 128
#define MTILES 391
#define DCAP   256

// ---------------- scratch globals ----------------
__device__ float g_h[(size_t)NNODES * WID];
__device__ float g_als[NNODES * 4];
__device__ float g_ald[NNODES * 4];
__device__ float g_esc[(size_t)ETOT * 4];    // fallback only (deg > DCAP)
__device__ int   g_dst[ETOT];
__device__ int   g_srcE[ETOT];
__device__ int   g_scsr[ETOT];
__device__ int   g_deg[NNODES];
__device__ int   g_rowptr[NNODES + 1];
__device__ int   g_cursor[NNODES];
__device__ int   g_i64flag;
__device__ int   g_incl[NNODES];
__device__ int   g_bsum[64];
__device__ int   g_boff[64];
// bf16 split operands (zero-init covers M padding)
__device__ __align__(16) __nv_bfloat16 g_Ahi[(size_t)NPAD * WID];
__device__ __align__(16) __nv_bfloat16 g_Alo[(size_t)NPAD * WID];
__device__ __align__(16) __nv_bfloat16 g_Bhi[WID * WID];   // [N=256][K]
__device__ __align__(16) __nv_bfloat16 g_Blo[WID * WID];

// ---------------- helpers ----------------
__device__ __forceinline__ uint32_t smem_u32(const void* p) {
    uint32_t a;
    asm("{ .reg .u64 t; cvta.to.shared.u64 t, %1; cvt.u32.u64 %0, t; }" : "=r"(a) : "l"(p));
    return a;
}
__device__ __forceinline__ void cp16(uint32_t s, const void* g) {
    asm volatile("cp.async.cg.shared.global [%0], [%1], 16;" :: "r"(s), "l"(g));
}
#define CP_COMMIT()  asm volatile("cp.async.commit_group;" ::: "memory")
#define CP_WAIT(n)   asm volatile("cp.async.wait_group %0;" :: "n"(n) : "memory")

__device__ __forceinline__ void mma16816(float* d, const uint32_t* a, const uint32_t* b) {
    asm volatile(
        "mma.sync.aligned.m16n8k16.row.col.f32.bf16.bf16.f32 "
        "{%0,%1,%2,%3}, {%4,%5,%6,%7}, {%8,%9}, {%0,%1,%2,%3};"
        : "+f"(d[0]), "+f"(d[1]), "+f"(d[2]), "+f"(d[3])
        : "r"(a[0]), "r"(a[1]), "r"(a[2]), "r"(a[3]), "r"(b[0]), "r"(b[1]));
}
__device__ __forceinline__ void ldsm_x4(uint32_t* r, uint32_t addr) {
    asm volatile("ldmatrix.sync.aligned.m8n8.x4.shared.b16 {%0,%1,%2,%3}, [%4];"
        : "=r"(r[0]), "=r"(r[1]), "=r"(r[2]), "=r"(r[3]) : "r"(addr));
}

// ---------------- dtype probe + clear deg ----------------
__global__ void k_probe_clear(const int* __restrict__ ei32) {
    int i = blockIdx.x * blockDim.x + threadIdx.x;
    if (i < NNODES) g_deg[i] = 0;
    if (i == 0) {
        int allzero = 1;
#pragma unroll
        for (int j = 0; j < 8; j++) allzero &= (ei32[2 * j + 1] == 0);
        g_i64flag = allzero;
    }
}

// ---------------- CSR build ----------------
__global__ void k_count(const void* __restrict__ ei) {
    int i = blockIdx.x * blockDim.x + threadIdx.x;
    if (i >= ETOT) return;
    int s, d;
    if (i < NEDG) {
        if (g_i64flag) {
            const long long* p = (const long long*)ei;
            s = (int)p[i]; d = (int)p[NEDG + i];
        } else {
            const int* p = (const int*)ei;
            s = p[i]; d = p[NEDG + i];
        }
    } else {
        s = i - NEDG; d = s;
    }
    g_srcE[i] = s;
    g_dst[i] = d;
    atomicAdd(&g_deg[d], 1);
}

__global__ __launch_bounds__(1024) void k_scan_blk() {
    __shared__ int wsum[32];
    int tid = threadIdx.x, lane = tid & 31, w = tid >> 5;
    int i = blockIdx.x * 1024 + tid;
    int v = (i < NNODES) ? g_deg[i] : 0;
    int x = v;
#pragma unroll
    for (int o = 1; o < 32; o <<= 1) {
        int t = __shfl_up_sync(0xffffffffu, x, o);
        if (lane >= o) x += t;
    }
    if (lane == 31) wsum[w] = x;
    __syncthreads();
    if (w == 0) {
        int s = wsum[lane];
#pragma unroll
        for (int o = 1; o < 32; o <<= 1) {
            int t = __shfl_up_sync(0xffffffffu, s, o);
            if (lane >= o) s += t;
        }
        wsum[lane] = s;
    }
    __syncthreads();
    int incl = x + (w ? wsum[w - 1] : 0);
    if (i < NNODES) g_incl[i] = incl;
    if (tid == 1023) g_bsum[blockIdx.x] = incl;
}

__global__ void k_scan_top(int nb) {
    if (threadIdx.x == 0) {
        int acc = 0;
        for (int b = 0; b < nb; b++) { g_boff[b] = acc; acc += g_bsum[b]; }
    }
}

__global__ void k_scan_fix() {
    int i = blockIdx.x * blockDim.x + threadIdx.x;
    if (i >= NNODES) return;
    int incl = g_incl[i] + g_boff[i >> 10];
    g_rowptr[i + 1] = incl;
    g_cursor[i] = incl - g_deg[i];
    if (i == 0) g_rowptr[0] = 0;
}

__global__ void k_fill() {
    int i = blockIdx.x * blockDim.x + threadIdx.x;
    if (i >= ETOT) return;
    int p = atomicAdd(&g_cursor[g_dst[i]], 1);
    g_scsr[p] = g_srcE[i];
}

// ---------------- fp32 -> bf16 hi/lo (layer 0; also zeroes g_als/ald) -------
__global__ void k_splitA(const float* __restrict__ in, int n4) {
    int i = blockIdx.x * blockDim.x + threadIdx.x;
    if (i < NNODES) {
        float4 z = make_float4(0.f, 0.f, 0.f, 0.f);
        ((float4*)g_als)[i] = z;
        ((float4*)g_ald)[i] = z;
    }
    if (i >= n4) return;
    float4 v = *(const float4*)(in + (size_t)i * 4);
    __nv_bfloat16 hx = __float2bfloat16(v.x), hy = __float2bfloat16(v.y);
    __nv_bfloat16 hz = __float2bfloat16(v.z), hw = __float2bfloat16(v.w);
    __nv_bfloat16 lx = __float2bfloat16(v.x - __bfloat162float(hx));
    __nv_bfloat16 ly = __float2bfloat16(v.y - __bfloat162float(hy));
    __nv_bfloat16 lz = __float2bfloat16(v.z - __bfloat162float(hz));
    __nv_bfloat16 lw = __float2bfloat16(v.w - __bfloat162float(hw));
    __nv_bfloat162* ph = (__nv_bfloat162*)g_Ahi + (size_t)i * 2;
    __nv_bfloat162* pl = (__nv_bfloat162*)g_Alo + (size_t)i * 2;
    ph[0] = __nv_bfloat162(hx, hy); ph[1] = __nv_bfloat162(hz, hw);
    pl[0] = __nv_bfloat162(lx, ly); pl[1] = __nv_bfloat162(lz, lw);
}

// W split for layers 1/2 — also clears g_als/g_ald for the next fused GEMM
__global__ void k_splitW(const float* __restrict__ W, int K) {
    int i = blockIdx.x * blockDim.x + threadIdx.x;
    if (i < NNODES) {
        float4 z = make_float4(0.f, 0.f, 0.f, 0.f);
        ((float4*)g_als)[i] = z;
        ((float4*)g_ald)[i] = z;
    }
    if (i >= K * WID) return;
    int k = i >> 8, n = i & 255;
    float v = W[i];
    __nv_bfloat16 h = __float2bfloat16(v);
    __nv_bfloat16 l = __float2bfloat16(v - __bfloat162float(h));
    g_Bhi[n * K + k] = h;
    g_Blo[n * K + k] = l;
}

// W split for layer 0 (no clear — splitA does it)
__global__ void k_splitW0(const float* __restrict__ W, int K) {
    int i = blockIdx.x * blockDim.x + threadIdx.x;
    if (i >= K * WID) return;
    int k = i >> 8, n = i & 255;
    float v = W[i];
    __nv_bfloat16 h = __float2bfloat16(v);
    __nv_bfloat16 l = __float2bfloat16(v - __bfloat162float(h));
    g_Bhi[n * K + k] = h;
    g_Blo[n * K + k] = l;
}

// ---------------- HMMA GEMM + fused attention epilogue ----------------
#define ROWB2  80
#define OFF_AH 0
#define OFF_AL 10240
#define OFF_BH 20480
#define OFF_BL 30720
#define STG2   40960
#define GSMEM2 81920

__device__ __forceinline__ void load_stage2(uint32_t sb, int bm, int bn, int K,
                                            int k0, int tid) {
#pragma unroll
    for (int i = 0; i < 2; i++) {
        int idx = tid + i * 256;
        int row = idx >> 2, seg = idx & 3;
        uint32_t so = row * ROWB2 + seg * 16;
        size_t ga = (size_t)(bm + row) * K + k0 + seg * 8;
        size_t gb = (size_t)(bn + row) * K + k0 + seg * 8;
        cp16(sb + OFF_AH + so, g_Ahi + ga);
        cp16(sb + OFF_AL + so, g_Alo + ga);
        cp16(sb + OFF_BH + so, g_Bhi + gb);
        cp16(sb + OFF_BL + so, g_Blo + gb);
    }
}

__global__ __launch_bounds__(256, 2) void k_gemm_mma(int K,
        const float* __restrict__ asrc, const float* __restrict__ adst) {
    extern __shared__ char smem[];
    uint32_t sb = smem_u32(smem);
    int tid = threadIdx.x, lane = tid & 31, w = tid >> 5;
    int bm = blockIdx.x * 128, bn = blockIdx.y * 128;
    int wm = (w >> 2) * 64, wn = (w & 3) * 32;

    float acc[4][4][4];
#pragma unroll
    for (int mt = 0; mt < 4; mt++)
#pragma unroll
        for (int nt = 0; nt < 4; nt++)
#pragma unroll
            for (int j = 0; j < 4; j++) acc[mt][nt][j] = 0.f;

    uint32_t aoff = (uint32_t)(wm + (lane & 15)) * ROWB2 + (lane >> 4) * 16;
    uint32_t boff = (uint32_t)(wn + ((lane >> 4) & 1) * 8 + (lane & 7)) * ROWB2
                  + ((lane >> 3) & 1) * 16;

    const int nc = K >> 5;
    load_stage2(sb, bm, bn, K, 0, tid);
    CP_COMMIT();

    for (int kc = 0; kc < nc; kc++) {
        if (kc + 1 < nc) {
            load_stage2(sb + ((kc + 1) & 1) * STG2, bm, bn, K, (kc + 1) << 5, tid);
            CP_COMMIT();
            CP_WAIT(1);
        } else {
            CP_WAIT(0);
        }
        __syncthreads();
        uint32_t st = sb + (kc & 1) * STG2;
#pragma unroll
        for (int ks = 0; ks < 2; ks++) {
            uint32_t kb = ks * 32;
            uint32_t ah[4][4], al[4][4];
#pragma unroll
            for (int mt = 0; mt < 4; mt++) {
                ldsm_x4(ah[mt], st + OFF_AH + aoff + mt * 16 * ROWB2 + kb);
                ldsm_x4(al[mt], st + OFF_AL + aoff + mt * 16 * ROWB2 + kb);
            }
#pragma unroll
            for (int p = 0; p < 2; p++) {
                uint32_t bh[4], bl[4];
                ldsm_x4(bh, st + OFF_BH + boff + p * 16 * ROWB2 + kb);
                ldsm_x4(bl, st + OFF_BL + boff + p * 16 * ROWB2 + kb);
                // pass-major schedule: accumulator reuse distance = 8 MMAs
#pragma unroll
                for (int q = 0; q < 2; q++)
#pragma unroll
                    for (int mt = 0; mt < 4; mt++)
                        mma16816(acc[mt][p * 2 + q], ah[mt], bh + q * 2);
#pragma unroll
                for (int q = 0; q < 2; q++)
#pragma unroll
                    for (int mt = 0; mt < 4; mt++)
                        mma16816(acc[mt][p * 2 + q], ah[mt], bl + q * 2);
#pragma unroll
                for (int q = 0; q < 2; q++)
#pragma unroll
                    for (int mt = 0; mt < 4; mt++)
                        mma16816(acc[mt][p * 2 + q], al[mt], bh + q * 2);
            }
        }
        __syncthreads();
    }

    // ---- fused epilogue: store g_h tile + per-row attention partial dots ---
    int r = lane >> 2, cq = lane & 3;
    int hh = ((bn + wn) >> 6) & 3;
    float2 as2[4], ad2[4];
#pragma unroll
    for (int nt = 0; nt < 4; nt++) {
        int col = bn + wn + nt * 8 + cq * 2;
        as2[nt] = *(const float2*)(asrc + col);
        ad2[nt] = *(const float2*)(adst + col);
    }
#pragma unroll
    for (int mt = 0; mt < 4; mt++) {
        int row0 = bm + wm + mt * 16 + r;
        float ps0 = 0.f, pd0 = 0.f, ps1 = 0.f, pd1 = 0.f;
#pragma unroll
        for (int nt = 0; nt < 4; nt++) {
            int col = bn + wn + nt * 8 + cq * 2;
            ps0 += acc[mt][nt][0] * as2[nt].x + acc[mt][nt][1] * as2[nt].y;
            pd0 += acc[mt][nt][0] * ad2[nt].x + acc[mt][nt][1] * ad2[nt].y;
            ps1 += acc[mt][nt][2] * as2[nt].x + acc[mt][nt][3] * as2[nt].y;
            pd1 += acc[mt][nt][2] * ad2[nt].x + acc[mt][nt][3] * ad2[nt].y;
            if (row0 < NNODES)
                *(float2*)(g_h + (size_t)row0 * WID + col) =
                    make_float2(acc[mt][nt][0], acc[mt][nt][1]);
            if (row0 + 8 < NNODES)
                *(float2*)(g_h + (size_t)(row0 + 8) * WID + col) =
                    make_float2(acc[mt][nt][2], acc[mt][nt][3]);
        }
        ps0 += __shfl_down_sync(0xffffffffu, ps0, 2);
        ps0 += __shfl_down_sync(0xffffffffu, ps0, 1);
        pd0 += __shfl_down_sync(0xffffffffu, pd0, 2);
        pd0 += __shfl_down_sync(0xffffffffu, pd0, 1);
        ps1 += __shfl_down_sync(0xffffffffu, ps1, 2);
        ps1 += __shfl_down_sync(0xffffffffu, ps1, 1);
        pd1 += __shfl_down_sync(0xffffffffu, pd1, 2);
        pd1 += __shfl_down_sync(0xffffffffu, pd1, 1);
        if (cq == 0) {
            if (row0 < NNODES) {
                atomicAdd(&g_als[row0 * 4 + hh], ps0);
                atomicAdd(&g_ald[row0 * 4 + hh], pd0);
            }
            if (row0 + 8 < NNODES) {
                atomicAdd(&g_als[(row0 + 8) * 4 + hh], ps1);
                atomicAdd(&g_ald[(row0 + 8) * 4 + hh], pd1);
            }
        }
    }
}

// --------- per-node softmax + aggregate + bias + ELU ---------
// dosplit=1: write bf16 hi/lo for next GEMM.  dosplit=0: fused pool+linear.
__global__ __launch_bounds__(128) void k_aggregate(const float* __restrict__ bias, int dosplit,
        const float* __restrict__ linw, const void* __restrict__ batch, float* out) {
    __shared__ int   sh_src[DCAP];
    __shared__ float sh_al[4][DCAP];
    __shared__ float s_inv[4];
    __shared__ float s_red[4];
    int n = blockIdx.x;
    int tid = threadIdx.x, lane = tid & 31, w = tid >> 5;
    int start = g_rowptr[n];
    int deg = g_rowptr[n + 1] - start;

    float v0, v1;
    int c = tid * 2;

    if (deg <= DCAP) {
        for (int i = tid; i < deg; i += 128) {
            int s = g_scsr[start + i];
            sh_src[i] = s;
            float4 a = ((const float4*)g_als)[s];
            sh_al[0][i] = a.x; sh_al[1][i] = a.y;
            sh_al[2][i] = a.z; sh_al[3][i] = a.w;
        }
        __syncthreads();

        float aldn = g_ald[n * 4 + w];
        float mx = -1e30f;
        for (int i = lane; i < deg; i += 32) {
            float v = sh_al[w][i] + aldn;
            v = v > 0.f ? v : 0.2f * v;
            sh_al[w][i] = v;
            mx = fmaxf(mx, v);
        }
#pragma unroll
        for (int o = 16; o; o >>= 1) mx = fmaxf(mx, __shfl_xor_sync(0xffffffffu, mx, o));
        float sum = 0.f;
        for (int i = lane; i < deg; i += 32) {
            float ex = expf(sh_al[w][i] - mx);
            sh_al[w][i] = ex;
            sum += ex;
        }
#pragma unroll
        for (int o = 16; o; o >>= 1) sum += __shfl_xor_sync(0xffffffffu, sum, o);
        if (lane == 0) s_inv[w] = 1.f / (sum + 1e-16f);
        __syncthreads();

        // aggregate with dual accumulators (2 independent gather chains)
        const float* alp = sh_al[w];
        float2 a0 = make_float2(0.f, 0.f), a1 = make_float2(0.f, 0.f);
        int i = 0;
#pragma unroll 2
        for (; i + 2 <= deg; i += 2) {
            float p = alp[i], q = alp[i + 1];
            float2 u = *((const float2*)(g_h + (size_t)sh_src[i] * WID) + tid);
            float2 v = *((const float2*)(g_h + (size_t)sh_src[i + 1] * WID) + tid);
            a0.x += p * u.x; a0.y += p * u.y;
            a1.x += q * v.x; a1.y += q * v.y;
        }
        if (i < deg) {
            float p = alp[i];
            float2 u = *((const float2*)(g_h + (size_t)sh_src[i] * WID) + tid);
            a0.x += p * u.x; a0.y += p * u.y;
        }
        float inv = s_inv[w];
        v0 = (a0.x + a1.x) * inv + bias[c];
        v1 = (a0.y + a1.y) * inv + bias[c + 1];
    } else {
        // -------- fallback: deg > DCAP ----------
        float aldn = g_ald[n * 4 + w];
        float mx = -1e30f;
        for (int i = lane; i < deg; i += 32) {
            float v = g_als[g_scsr[start + i] * 4 + w] + aldn;
            v = v > 0.f ? v : 0.2f * v;
            g_esc[(size_t)(start + i) * 4 + w] = v;
            mx = fmaxf(mx, v);
        }
#pragma unroll
        for (int o = 16; o; o >>= 1) mx = fmaxf(mx, __shfl_xor_sync(0xffffffffu, mx, o));
        float sum = 0.f;
        for (int i = lane; i < deg; i += 32) {
            float ex = expf(g_esc[(size_t)(start + i) * 4 + w] - mx);
            g_esc[(size_t)(start + i) * 4 + w] = ex;
            sum += ex;
        }
#pragma unroll
        for (int o = 16; o; o >>= 1) sum += __shfl_xor_sync(0xffffffffu, sum, o);
        if (lane == 0) s_inv[w] = 1.f / (sum + 1e-16f);
        __syncthreads();

        float2 acc = make_float2(0.f, 0.f);
        for (int i = 0; i < deg; i++) {
            int s = g_scsr[start + i];
            float a = g_esc[(size_t)(start + i) * 4 + w];
            float2 v = *((const float2*)(g_h + (size_t)s * WID) + tid);
            acc.x += a * v.x;
            acc.y += a * v.y;
        }
        float inv = s_inv[w];
        v0 = acc.x * inv + bias[c];
        v1 = acc.y * inv + bias[c + 1];
    }

    v0 = v0 > 0.f ? v0 : expm1f(v0);           // ELU
    v1 = v1 > 0.f ? v1 : expm1f(v1);

    if (dosplit) {
        __nv_bfloat16 H0 = __float2bfloat16(v0), H1 = __float2bfloat16(v1);
        *((__nv_bfloat162*)(g_Ahi + (size_t)n * WID + c)) = __nv_bfloat162(H0, H1);
        *((__nv_bfloat162*)(g_Alo + (size_t)n * WID + c)) =
            __nv_bfloat162(__float2bfloat16(v0 - __bfloat162float(H0)),
                           __float2bfloat16(v1 - __bfloat162float(H1)));
    } else {
        // fused pooling + linear head: partial = v . lin_w, block reduce, atomic
        float part = v0 * linw[c] + v1 * linw[c + 1];
#pragma unroll
        for (int o = 16; o; o >>= 1) part += __shfl_xor_sync(0xffffffffu, part, o);
        if (lane == 0) s_red[w] = part;
        __syncthreads();
        if (tid == 0) {
            float tot = (s_red[0] + s_red[1]) + (s_red[2] + s_red[3]);
            int g = g_i64flag ? (int)((const long long*)batch)[n]
                              : ((const int*)batch)[n];
            atomicAdd(&out[g], tot);
        }
    }
}

// ---------------- out init ----------------
__global__ void k_init_out(float* out, const float* __restrict__ lin_b) {
    int i = threadIdx.x;
    if (i < NG) out[i] = lin_b[0];
}

// ---------------- launch ----------------
extern "C" void kernel_launch(void* const* d_in, const int* in_sizes, int n_in,
                              void* d_out, int out_size) {
    const float* x     = (const float*)d_in[0];
    const void*  ei    = d_in[1];
    const void*  batch = d_in[3];
    const float* W[3]    = {(const float*)d_in[4],  (const float*)d_in[8],  (const float*)d_in[12]};
    const float* asrc[3] = {(const float*)d_in[5],  (const float*)d_in[9],  (const float*)d_in[13]};
    const float* adst[3] = {(const float*)d_in[6],  (const float*)d_in[10], (const float*)d_in[14]};
    const float* bb[3]   = {(const float*)d_in[7],  (const float*)d_in[11], (const float*)d_in[15]};
    const float* linw = (const float*)d_in[16];
    const float* linb = (const float*)d_in[17];
    float* out = (float*)d_out;

    static int smem_set = 0;
    if (!smem_set) {
        cudaFuncSetAttribute(k_gemm_mma, cudaFuncAttributeMaxDynamicSharedMemorySize, GSMEM2);
        smem_set = 1;
    }

    dim3 ggrid(MTILES, 2);
    int nodeGrid = (NNODES + 255) / 256;

    // probe + clear, layer-0 split (also zeroes g_als/ald), W0 split, GEMM0
    k_probe_clear<<<nodeGrid, 256>>>((const int*)ei);
    k_splitA<<<(NNODES * 128 / 4 + 255) / 256, 256>>>(x, NNODES * 128 / 4);
    k_splitW0<<<(128 * WID + 255) / 256, 256>>>(W[0], 128);
    k_gemm_mma<<<ggrid, 256, GSMEM2>>>(128, asrc[0], adst[0]);

    // CSR build (before first aggregate)
    k_count<<<(ETOT + 255) / 256, 256>>>(ei);
    int nb = (NNODES + 1023) / 1024;
    k_scan_blk<<<nb, 1024>>>();
    k_scan_top<<<1, 32>>>(nb);
    k_scan_fix<<<nodeGrid, 256>>>();
    k_fill<<<(ETOT + 255) / 256, 256>>>();

    // layer 0 tail
    k_aggregate<<<NNODES, 128>>>(bb[0], 1, nullptr, nullptr, nullptr);

    // layer 1 (K=256); splitW also clears g_als/ald
    k_splitW<<<(256 * WID + 255) / 256, 256>>>(W[1], 256);
    k_gemm_mma<<<ggrid, 256, GSMEM2>>>(256, asrc[1], adst[1]);
    k_aggregate<<<NNODES, 128>>>(bb[1], 1, nullptr, nullptr, nullptr);

    // layer 2 (K=256): aggregate fuses pooling + linear head
    k_splitW<<<(256 * WID + 255) / 256, 256>>>(W[2], 256);
    k_gemm_mma<<<ggrid, 256, GSMEM2>>>(256, asrc[2], adst[2]);
    k_init_out<<<1, 256>>>(out, linb);
    k_aggregate<<<NNODES, 128>>>(bb[2], 0, linw, batch, out);
}